// round 5
// baseline (speedup 1.0000x reference)
#include <cuda_runtime.h>

#define NN    100000
#define EMAX  1000000
#define D     128
#define DE    32
#define KF    288          // 2*D + DE
#define HID   512
#define PITCH 132          // smem row pitch (floats) for 128-wide tiles

typedef unsigned long long ull;

// Scratch (no cudaMalloc allowed)
__device__ float g_agg[(size_t)NN * D];
__device__ float g_cnt[NN];
__device__ int   g_src[EMAX];
__device__ int   g_dst[EMAX];

// ---------------------------------------------------------------------------
// f32x2 packed-FMA helpers (Blackwell: 2x fp32 FMA throughput vs FFMA-3reg)
// ---------------------------------------------------------------------------
__device__ __forceinline__ ull pk(float lo, float hi) {
    ull r; asm("mov.b64 %0, {%1, %2};" : "=l"(r) : "f"(lo), "f"(hi)); return r;
}
__device__ __forceinline__ void upk(ull v, float& lo, float& hi) {
    asm("mov.b64 {%0, %1}, %2;" : "=f"(lo), "=f"(hi) : "l"(v));
}
__device__ __forceinline__ ull fma2(ull a, ull b, ull c) {
    ull d; asm("fma.rn.f32x2 %0, %1, %2, %3;" : "=l"(d) : "l"(a), "l"(b), "l"(c)); return d;
}
__device__ __forceinline__ float sigm(float x) {
    return 1.0f / (1.0f + __expf(-x));
}

// 16-deep K-chunk micro-kernel: C[128x128] tile, 256 threads, 8x8 per thread.
__device__ __forceinline__ void mma16(ull acc[4][8], const float* sA,
                                      const float* sB, int m0, int n0) {
#pragma unroll
    for (int kk = 0; kk < 16; kk++) {
        float4 a0 = *(const float4*)(sA + kk * PITCH + m0);
        float4 a1 = *(const float4*)(sA + kk * PITCH + m0 + 4);
        ull ap0 = pk(a0.x, a0.y), ap1 = pk(a0.z, a0.w);
        ull ap2 = pk(a1.x, a1.y), ap3 = pk(a1.z, a1.w);
        float4 b0 = *(const float4*)(sB + kk * D + n0);
        float4 b1 = *(const float4*)(sB + kk * D + n0 + 4);
        float bs[8] = {b0.x, b0.y, b0.z, b0.w, b1.x, b1.y, b1.z, b1.w};
#pragma unroll
        for (int j = 0; j < 8; j++) {
            ull bb = pk(bs[j], bs[j]);
            acc[0][j] = fma2(ap0, bb, acc[0][j]);
            acc[1][j] = fma2(ap1, bb, acc[1][j]);
            acc[2][j] = fma2(ap2, bb, acc[2][j]);
            acc[3][j] = fma2(ap3, bb, acc[3][j]);
        }
    }
}

// ---------------------------------------------------------------------------
// Kernel A: convert edge_index (int64 OR int32, auto-detected) -> int32 arrays
// Detection: interpret first 4 values as int64; all in [0, NN) <=> truly int64
// (an int32 pair read as int64 is lo + hi*2^32, out of range unless hi==0).
// Indices are clamped so downstream gathers can never IMA.
// ---------------------------------------------------------------------------
__global__ void cvt_kernel(const void* __restrict__ ei_raw, int E) {
    const long long* p64 = (const long long*)ei_raw;
    const int*       p32 = (const int*)ei_raw;
    bool is64 = true;
#pragma unroll
    for (int j = 0; j < 4; j++) {
        long long v = p64[j];
        if (v < 0 || v >= NN) is64 = false;
    }
    int i = blockIdx.x * 256 + threadIdx.x;
    if (i < E) {
        int s, d;
        if (is64) { s = (int)p64[i]; d = (int)p64[(size_t)E + i]; }
        else      { s = p32[i];      d = p32[(size_t)E + i]; }
        g_src[i] = min(max(s, 0), NN - 1);
        g_dst[i] = min(max(d, 0), NN - 1);
    }
}

// ---------------------------------------------------------------------------
// Kernel 0: zero the aggregation scratch (must happen every call/replay)
// ---------------------------------------------------------------------------
__global__ void zero_kernel(int Nn) {
    size_t i = (size_t)blockIdx.x * 256 + threadIdx.x;
    size_t nagg4 = (size_t)Nn * D / 4;
    size_t ncnt4 = (size_t)Nn / 4;
    if (i < nagg4) {
        ((float4*)g_agg)[i] = make_float4(0.f, 0.f, 0.f, 0.f);
    } else if (i - nagg4 < ncnt4) {
        ((float4*)g_cnt)[i - nagg4] = make_float4(0.f, 0.f, 0.f, 0.f);
    }
}

// ---------------------------------------------------------------------------
// Kernel 1: per-edge message MLP + scatter-add
// ---------------------------------------------------------------------------
__global__ __launch_bounds__(256, 1)
void edge_kernel(const float* __restrict__ x, const float* __restrict__ ea,
                 const float* __restrict__ W1, const float* __restrict__ b1,
                 const float* __restrict__ W2, const float* __restrict__ b2,
                 const float* __restrict__ W3, const float* __restrict__ b3,
                 int E) {
    extern __shared__ float sm[];
    float* sM  = sm;                    // 128 x PITCH (inter-GEMM activations)
    float* sA  = sM + D * PITCH;        // 16 x PITCH  (A chunk, [k][m])
    float* sB  = sA + 16 * PITCH;       // 16 x D      (W chunk, [k][n])
    int*   sSrc = (int*)(sB + 16 * D);  // 128
    int*   sDst = sSrc + 128;           // 128

    const int tid = threadIdx.x;
    const int e0  = blockIdx.x * 128;
    const int nE  = min(128, E - e0);

    if (tid < 128) {
        if (tid < nE) {
            sSrc[tid] = g_src[e0 + tid];
            sDst[tid] = g_dst[e0 + tid];
        } else {
            sSrc[tid] = 0; sDst[tid] = 0;
        }
    }
    __syncthreads();

    if (tid < nE) atomicAdd(&g_cnt[sDst[tid]], 1.0f);

    const int tx = tid & 15, ty = tid >> 4;
    const int m0 = ty * 8, n0 = tx * 8;

    ull acc[4][8];
#pragma unroll
    for (int i = 0; i < 4; i++)
#pragma unroll
        for (int j = 0; j < 8; j++) acc[i][j] = 0ull;

    // ---------------- GEMM1: feats[128x288] @ W1[288x128] ----------------
    for (int kc = 0; kc < KF; kc += 16) {
#pragma unroll
        for (int i = 0; i < 2; i++) {        // gather A chunk, transposed
            int task = tid + i * 256;
            int m = task & 127;
            int kg = task >> 7;              // 0..3
            int k = kc + kg * 4;
            float4 v = make_float4(0.f, 0.f, 0.f, 0.f);
            if (m < nE) {
                if (k < D)          v = *(const float4*)(x + (size_t)sSrc[m] * D + k);
                else if (k < 2 * D) v = *(const float4*)(x + (size_t)sDst[m] * D + (k - D));
                else                v = *(const float4*)(ea + (size_t)(e0 + m) * DE + (k - 2 * D));
            }
            sA[(kg * 4 + 0) * PITCH + m] = v.x;
            sA[(kg * 4 + 1) * PITCH + m] = v.y;
            sA[(kg * 4 + 2) * PITCH + m] = v.z;
            sA[(kg * 4 + 3) * PITCH + m] = v.w;
        }
#pragma unroll
        for (int i = 0; i < 2; i++) {        // stage W1 chunk
            int task = tid + i * 256;
            int n4 = task & 31, k = task >> 5;
            *(float4*)(sB + k * D + n4 * 4) =
                *(const float4*)(W1 + (size_t)(kc + k) * D + n4 * 4);
        }
        __syncthreads();
        mma16(acc, sA, sB, m0, n0);
        __syncthreads();
    }
    {   // epilogue 1: + b1 -> sM
        float4 c0 = *(const float4*)(b1 + n0);
        float4 c1 = *(const float4*)(b1 + n0 + 4);
        float bv[8] = {c0.x, c0.y, c0.z, c0.w, c1.x, c1.y, c1.z, c1.w};
#pragma unroll
        for (int i = 0; i < 4; i++)
#pragma unroll
            for (int j = 0; j < 8; j++) {
                float lo, hi; upk(acc[i][j], lo, hi);
                sM[(m0 + 2 * i)     * PITCH + n0 + j] = lo + bv[j];
                sM[(m0 + 2 * i + 1) * PITCH + n0 + j] = hi + bv[j];
                acc[i][j] = 0ull;
            }
    }
    __syncthreads();

    // ---------------- GEMM2: sigmoid(M1 @ W2 + b2), in place ----------------
    for (int kc = 0; kc < D; kc += 16) {
#pragma unroll
        for (int i = 0; i < 2; i++) {        // transpose-stage A from sM
            int task = tid + i * 256;
            int m = task & 127, kg = task >> 7, k = kc + kg * 4;
            float4 v = *(const float4*)(sM + m * PITCH + k);
            sA[(kg * 4 + 0) * PITCH + m] = v.x;
            sA[(kg * 4 + 1) * PITCH + m] = v.y;
            sA[(kg * 4 + 2) * PITCH + m] = v.z;
            sA[(kg * 4 + 3) * PITCH + m] = v.w;
        }
#pragma unroll
        for (int i = 0; i < 2; i++) {
            int task = tid + i * 256;
            int n4 = task & 31, k = task >> 5;
            *(float4*)(sB + k * D + n4 * 4) =
                *(const float4*)(W2 + (size_t)(kc + k) * D + n4 * 4);
        }
        __syncthreads();
        mma16(acc, sA, sB, m0, n0);
        __syncthreads();
    }
    {   // epilogue 2: sigmoid(+b2) -> sM (sM fully consumed above)
        float4 c0 = *(const float4*)(b2 + n0);
        float4 c1 = *(const float4*)(b2 + n0 + 4);
        float bv[8] = {c0.x, c0.y, c0.z, c0.w, c1.x, c1.y, c1.z, c1.w};
#pragma unroll
        for (int i = 0; i < 4; i++)
#pragma unroll
            for (int j = 0; j < 8; j++) {
                float lo, hi; upk(acc[i][j], lo, hi);
                sM[(m0 + 2 * i)     * PITCH + n0 + j] = sigm(lo + bv[j]);
                sM[(m0 + 2 * i + 1) * PITCH + n0 + j] = sigm(hi + bv[j]);
                acc[i][j] = 0ull;
            }
    }
    __syncthreads();

    // ---------------- GEMM3: M2 @ W3 + b3 -> scatter ----------------
    for (int kc = 0; kc < D; kc += 16) {
#pragma unroll
        for (int i = 0; i < 2; i++) {
            int task = tid + i * 256;
            int m = task & 127, kg = task >> 7, k = kc + kg * 4;
            float4 v = *(const float4*)(sM + m * PITCH + k);
            sA[(kg * 4 + 0) * PITCH + m] = v.x;
            sA[(kg * 4 + 1) * PITCH + m] = v.y;
            sA[(kg * 4 + 2) * PITCH + m] = v.z;
            sA[(kg * 4 + 3) * PITCH + m] = v.w;
        }
#pragma unroll
        for (int i = 0; i < 2; i++) {
            int task = tid + i * 256;
            int n4 = task & 31, k = task >> 5;
            *(float4*)(sB + k * D + n4 * 4) =
                *(const float4*)(W3 + (size_t)(kc + k) * D + n4 * 4);
        }
        __syncthreads();
        mma16(acc, sA, sB, m0, n0);
        __syncthreads();
    }
    {   // epilogue 3: + b3, vector-atomic scatter into g_agg[dst]
        float4 c0 = *(const float4*)(b3 + n0);
        float4 c1 = *(const float4*)(b3 + n0 + 4);
        float bv[8] = {c0.x, c0.y, c0.z, c0.w, c1.x, c1.y, c1.z, c1.w};
#pragma unroll
        for (int i = 0; i < 4; i++) {
            float lo[8], hi[8];
#pragma unroll
            for (int j = 0; j < 8; j++) upk(acc[i][j], lo[j], hi[j]);
            int mA = m0 + 2 * i, mB = m0 + 2 * i + 1;
            if (mA < nE) {
                float* base = g_agg + (size_t)sDst[mA] * D + n0;
                atomicAdd((float4*)base,
                          make_float4(lo[0] + bv[0], lo[1] + bv[1], lo[2] + bv[2], lo[3] + bv[3]));
                atomicAdd((float4*)(base + 4),
                          make_float4(lo[4] + bv[4], lo[5] + bv[5], lo[6] + bv[6], lo[7] + bv[7]));
            }
            if (mB < nE) {
                float* base = g_agg + (size_t)sDst[mB] * D + n0;
                atomicAdd((float4*)base,
                          make_float4(hi[0] + bv[0], hi[1] + bv[1], hi[2] + bv[2], hi[3] + bv[3]));
                atomicAdd((float4*)(base + 4),
                          make_float4(hi[4] + bv[4], hi[5] + bv[5], hi[6] + bv[6], hi[7] + bv[7]));
            }
        }
    }
}

// ---------------------------------------------------------------------------
// Kernel 2: node update
// ---------------------------------------------------------------------------
__global__ __launch_bounds__(256, 1)
void node_kernel(const float* __restrict__ x,
                 const float* __restrict__ Wf1, const float* __restrict__ bf1,
                 const float* __restrict__ Wf2, const float* __restrict__ bf2,
                 const float* __restrict__ g0, const float* __restrict__ be0,
                 const float* __restrict__ g1, const float* __restrict__ be1,
                 float* __restrict__ out, int Nn) {
    extern __shared__ float sm[];
    float* sH = sm;                  // 128 x PITCH : normalized h
    float* sT = sH + D * PITCH;      // 128 x PITCH : hidden chunk / ff
    float* sA = sT + D * PITCH;      // 16 x PITCH
    float* sB = sA + 16 * PITCH;     // 16 x D

    const int tid = threadIdx.x;
    const int lane = tid & 31, wid = tid >> 5;
    const int r0 = blockIdx.x * 128;
    const int nR = min(128, Nn - r0);
    const int tx = tid & 15, ty = tid >> 4;
    const int m0 = ty * 8, n0 = tx * 8;

    // Phase 1: warp-per-row LayerNorm(x + dh) -> sH
    for (int r = wid; r < 128; r += 8) {
        if (r < nR) {
            int g = r0 + r;
            float4 xv = *(const float4*)(x + (size_t)g * D + lane * 4);
            float4 av = *(const float4*)(g_agg + (size_t)g * D + lane * 4);
            float inv = 1.0f / fmaxf(g_cnt[g], 1.0f);
            float v0 = xv.x + av.x * inv, v1 = xv.y + av.y * inv;
            float v2 = xv.z + av.z * inv, v3 = xv.w + av.w * inv;
            float s = v0 + v1 + v2 + v3;
            float q = v0 * v0 + v1 * v1 + v2 * v2 + v3 * v3;
#pragma unroll
            for (int o = 16; o > 0; o >>= 1) {
                s += __shfl_xor_sync(0xffffffffu, s, o);
                q += __shfl_xor_sync(0xffffffffu, q, o);
            }
            float mu = s * (1.0f / 128.0f);
            float rs = rsqrtf(q * (1.0f / 128.0f) - mu * mu + 1e-5f);
            float4 gg = *(const float4*)(g0 + lane * 4);
            float4 bb = *(const float4*)(be0 + lane * 4);
            float4 h;
            h.x = (v0 - mu) * rs * gg.x + bb.x;
            h.y = (v1 - mu) * rs * gg.y + bb.y;
            h.z = (v2 - mu) * rs * gg.z + bb.z;
            h.w = (v3 - mu) * rs * gg.w + bb.w;
            *(float4*)(sH + r * PITCH + lane * 4) = h;
        } else {
            *(float4*)(sH + r * PITCH + lane * 4) = make_float4(0.f, 0.f, 0.f, 0.f);
        }
    }
    __syncthreads();

    // Phase 2: ff = sigmoid(h@Wf1+bf1)@Wf2 in 4 chunks of 128 hidden cols
    ull acc2[4][8];
#pragma unroll
    for (int i = 0; i < 4; i++)
#pragma unroll
        for (int j = 0; j < 8; j++) acc2[i][j] = 0ull;

    for (int c = 0; c < 4; c++) {
        ull acc[4][8];
#pragma unroll
        for (int i = 0; i < 4; i++)
#pragma unroll
            for (int j = 0; j < 8; j++) acc[i][j] = 0ull;

        for (int kc = 0; kc < D; kc += 16) {     // T = H @ Wf1[:, c*128:+128]
#pragma unroll
            for (int i = 0; i < 2; i++) {
                int task = tid + i * 256;
                int m = task & 127, kg = task >> 7, k = kc + kg * 4;
                float4 v = *(const float4*)(sH + m * PITCH + k);
                sA[(kg * 4 + 0) * PITCH + m] = v.x;
                sA[(kg * 4 + 1) * PITCH + m] = v.y;
                sA[(kg * 4 + 2) * PITCH + m] = v.z;
                sA[(kg * 4 + 3) * PITCH + m] = v.w;
            }
#pragma unroll
            for (int i = 0; i < 2; i++) {
                int task = tid + i * 256;
                int n4 = task & 31, k = task >> 5;
                *(float4*)(sB + k * D + n4 * 4) =
                    *(const float4*)(Wf1 + (size_t)(kc + k) * HID + c * 128 + n4 * 4);
            }
            __syncthreads();
            mma16(acc, sA, sB, m0, n0);
            __syncthreads();
        }
        {   // T epilogue: sigmoid(+bf1) -> sT
            float4 c0 = *(const float4*)(bf1 + c * 128 + n0);
            float4 c1 = *(const float4*)(bf1 + c * 128 + n0 + 4);
            float bv[8] = {c0.x, c0.y, c0.z, c0.w, c1.x, c1.y, c1.z, c1.w};
#pragma unroll
            for (int i = 0; i < 4; i++)
#pragma unroll
                for (int j = 0; j < 8; j++) {
                    float lo, hi; upk(acc[i][j], lo, hi);
                    sT[(m0 + 2 * i)     * PITCH + n0 + j] = sigm(lo + bv[j]);
                    sT[(m0 + 2 * i + 1) * PITCH + n0 + j] = sigm(hi + bv[j]);
                }
        }
        __syncthreads();

        for (int kc = 0; kc < D; kc += 16) {     // acc2 += T @ Wf2[c*128:+128, :]
#pragma unroll
            for (int i = 0; i < 2; i++) {
                int task = tid + i * 256;
                int m = task & 127, kg = task >> 7, k = kc + kg * 4;
                float4 v = *(const float4*)(sT + m * PITCH + k);
                sA[(kg * 4 + 0) * PITCH + m] = v.x;
                sA[(kg * 4 + 1) * PITCH + m] = v.y;
                sA[(kg * 4 + 2) * PITCH + m] = v.z;
                sA[(kg * 4 + 3) * PITCH + m] = v.w;
            }
#pragma unroll
            for (int i = 0; i < 2; i++) {
                int task = tid + i * 256;
                int n4 = task & 31, k = task >> 5;
                *(float4*)(sB + k * D + n4 * 4) =
                    *(const float4*)(Wf2 + (size_t)(c * 128 + kc + k) * D + n4 * 4);
            }
            __syncthreads();
            mma16(acc2, sA, sB, m0, n0);
            __syncthreads();
        }
    }

    // Phase 3: ff (+bf2) -> sT, then out = LN(h + ff)
    {
        float4 c0 = *(const float4*)(bf2 + n0);
        float4 c1 = *(const float4*)(bf2 + n0 + 4);
        float bv[8] = {c0.x, c0.y, c0.z, c0.w, c1.x, c1.y, c1.z, c1.w};
#pragma unroll
        for (int i = 0; i < 4; i++)
#pragma unroll
            for (int j = 0; j < 8; j++) {
                float lo, hi; upk(acc2[i][j], lo, hi);
                sT[(m0 + 2 * i)     * PITCH + n0 + j] = lo + bv[j];
                sT[(m0 + 2 * i + 1) * PITCH + n0 + j] = hi + bv[j];
            }
    }
    __syncthreads();

    for (int r = wid; r < nR; r += 8) {
        float4 hh = *(const float4*)(sH + r * PITCH + lane * 4);
        float4 ff = *(const float4*)(sT + r * PITCH + lane * 4);
        float v0 = hh.x + ff.x, v1 = hh.y + ff.y;
        float v2 = hh.z + ff.z, v3 = hh.w + ff.w;
        float s = v0 + v1 + v2 + v3;
        float q = v0 * v0 + v1 * v1 + v2 * v2 + v3 * v3;
#pragma unroll
        for (int o = 16; o > 0; o >>= 1) {
            s += __shfl_xor_sync(0xffffffffu, s, o);
            q += __shfl_xor_sync(0xffffffffu, q, o);
        }
        float mu = s * (1.0f / 128.0f);
        float rs = rsqrtf(q * (1.0f / 128.0f) - mu * mu + 1e-5f);
        float4 gg = *(const float4*)(g1 + lane * 4);
        float4 bb = *(const float4*)(be1 + lane * 4);
        float4 o4;
        o4.x = (v0 - mu) * rs * gg.x + bb.x;
        o4.y = (v1 - mu) * rs * gg.y + bb.y;
        o4.z = (v2 - mu) * rs * gg.z + bb.z;
        o4.w = (v3 - mu) * rs * gg.w + bb.w;
        *(float4*)(out + (size_t)(r0 + r) * D + lane * 4) = o4;
    }
}

// ---------------------------------------------------------------------------
extern "C" void kernel_launch(void* const* d_in, const int* in_sizes, int n_in,
                              void* d_out, int out_size) {
    // Identify the three big tensors by element count (robust to ordering):
    // edge_attr (E*32) > x (N*128) > edge_index (2E).
    int i_big[3] = {0, 1, 2};
    for (int a = 0; a < 2; a++)
        for (int b = a + 1; b < 3; b++)
            if (in_sizes[i_big[b]] > in_sizes[i_big[a]]) {
                int t = i_big[a]; i_big[a] = i_big[b]; i_big[b] = t;
            }
    const float* ea = (const float*)d_in[i_big[0]];
    const float* x  = (const float*)d_in[i_big[1]];
    const void*  ei = d_in[i_big[2]];

    const float* W1  = (const float*)d_in[3];
    const float* b1  = (const float*)d_in[4];
    const float* W2  = (const float*)d_in[5];
    const float* b2  = (const float*)d_in[6];
    const float* W3  = (const float*)d_in[7];
    const float* b3  = (const float*)d_in[8];
    const float* Wf1 = (const float*)d_in[9];
    const float* bf1 = (const float*)d_in[10];
    const float* Wf2 = (const float*)d_in[11];
    const float* bf2 = (const float*)d_in[12];
    const float* g0  = (const float*)d_in[13];
    const float* be0 = (const float*)d_in[14];
    const float* g1  = (const float*)d_in[15];
    const float* be1 = (const float*)d_in[16];
    float* out = (float*)d_out;

    int E  = in_sizes[i_big[0]] / DE;   // edge_attr is E x 32
    int Nn = in_sizes[i_big[1]] / D;    // x is N x 128
    if (E > EMAX) E = EMAX;

    int smemE = (D * PITCH + 16 * PITCH + 16 * D) * (int)sizeof(float)
                + 256 * (int)sizeof(int);
    int smemN = (D * PITCH * 2 + 16 * PITCH + 16 * D) * (int)sizeof(float);
    cudaFuncSetAttribute(edge_kernel, cudaFuncAttributeMaxDynamicSharedMemorySize, smemE);
    cudaFuncSetAttribute(node_kernel, cudaFuncAttributeMaxDynamicSharedMemorySize, smemN);

    cvt_kernel<<<(E + 255) / 256, 256>>>(ei, E);
    size_t tot4 = (size_t)Nn * D / 4 + (size_t)Nn / 4;
    zero_kernel<<<(unsigned)((tot4 + 255) / 256), 256>>>(Nn);
    edge_kernel<<<(E + 127) / 128, 256, smemE>>>(x, ea, W1, b1, W2, b2, W3, b3, E);
    node_kernel<<<(Nn + 127) / 128, 256, smemN>>>(x, Wf1, bf1, Wf2, bf2,
                                                  g0, be0, g1, be1, out, Nn);
}

// round 7
// speedup vs baseline: 2.2071x; 2.2071x over previous
#include <cuda_runtime.h>

#define NN    100000
#define EMAX  1000000
#define D     128
#define DE    32
#define KF    288          // 2*D + DE
#define HID   512
#define PA    20           // sA pitch (tf32 words): [m][k] tiles, conflict-free frag loads
#define PB    136          // sB pitch: [k][n], conflict-free frag loads
#define PM    129          // activation smem pitch (fp32), scalar access conflict-free

// Scratch (no cudaMalloc allowed)
__device__ float g_agg[(size_t)NN * D];
__device__ float g_cnt[NN];
__device__ int   g_src[EMAX];
__device__ int   g_dst[EMAX];

__device__ __forceinline__ float sigm(float x) { return 1.0f / (1.0f + __expf(-x)); }

__device__ __forceinline__ unsigned f2tf(float f) {
    unsigned u; asm("cvt.rna.tf32.f32 %0, %1;" : "=r"(u) : "f"(f)); return u;
}

__device__ __forceinline__ void mma8(float c[4], const unsigned a[4], const unsigned b[2]) {
    asm volatile(
        "mma.sync.aligned.m16n8k8.row.col.f32.tf32.tf32.f32 "
        "{%0,%1,%2,%3}, {%4,%5,%6,%7}, {%8,%9}, {%0,%1,%2,%3};"
        : "+f"(c[0]), "+f"(c[1]), "+f"(c[2]), "+f"(c[3])
        : "r"(a[0]), "r"(a[1]), "r"(a[2]), "r"(a[3]), "r"(b[0]), "r"(b[1]));
}

// One K=16 chunk for a 32x64 warp tile (2 m-frags x 8 n-frags).
__device__ __forceinline__ void wmma_chunk(float acc[2][8][4], const unsigned* sA,
                                           const unsigned* sB, int warp_m, int warp_n,
                                           int lane) {
    const int gr = lane >> 2, ct = lane & 3;
#pragma unroll
    for (int ks = 0; ks < 16; ks += 8) {
        unsigned a[2][4], b[8][2];
#pragma unroll
        for (int mt = 0; mt < 2; mt++) {
            int r = warp_m + mt * 16 + gr;
            a[mt][0] = sA[r * PA + ks + ct];
            a[mt][1] = sA[(r + 8) * PA + ks + ct];
            a[mt][2] = sA[r * PA + ks + 4 + ct];
            a[mt][3] = sA[(r + 8) * PA + ks + 4 + ct];
        }
#pragma unroll
        for (int nt = 0; nt < 8; nt++) {
            int n = warp_n + nt * 8 + gr;
            b[nt][0] = sB[(ks + ct) * PB + n];
            b[nt][1] = sB[(ks + 4 + ct) * PB + n];
        }
#pragma unroll
        for (int mt = 0; mt < 2; mt++)
#pragma unroll
            for (int nt = 0; nt < 8; nt++) mma8(acc[mt][nt], a[mt], b[nt]);
    }
}

__device__ __forceinline__ void acc_zero(float acc[2][8][4]) {
#pragma unroll
    for (int i = 0; i < 2; i++)
#pragma unroll
        for (int j = 0; j < 8; j++)
#pragma unroll
            for (int k = 0; k < 4; k++) acc[i][j][k] = 0.f;
}

// Epilogue: acc(+bias[bias0+col]) [optionally sigmoid] -> sOut[m][col] (pitch PM)
__device__ __forceinline__ void epi_store(const float acc[2][8][4], float* sOut,
                                          const float* __restrict__ bias, int bias0,
                                          int warp_m, int warp_n, int lane, bool do_sig) {
    const int gr = lane >> 2, ct2 = (lane & 3) * 2;
#pragma unroll
    for (int mt = 0; mt < 2; mt++)
#pragma unroll
        for (int nt = 0; nt < 8; nt++) {
            int r = warp_m + mt * 16 + gr;
            int c = warp_n + nt * 8 + ct2;
            float bv0 = bias[bias0 + c], bv1 = bias[bias0 + c + 1];
            float v0 = acc[mt][nt][0] + bv0, v1 = acc[mt][nt][1] + bv1;
            float v2 = acc[mt][nt][2] + bv0, v3 = acc[mt][nt][3] + bv1;
            if (do_sig) { v0 = sigm(v0); v1 = sigm(v1); v2 = sigm(v2); v3 = sigm(v3); }
            sOut[r * PM + c] = v0;       sOut[r * PM + c + 1] = v1;
            sOut[(r + 8) * PM + c] = v2; sOut[(r + 8) * PM + c + 1] = v3;
        }
}

// Stage an A chunk (rows of an activation buffer, fp32 pitch PM) into sA as tf32.
__device__ __forceinline__ void stageA_sm(const float* sSrcM, unsigned* sA, int kc,
                                          int am, int ah) {
    unsigned u[8];
#pragma unroll
    for (int j = 0; j < 8; j++) u[j] = f2tf(sSrcM[am * PM + kc + ah * 8 + j]);
    *(uint4*)(sA + am * PA + ah * 8)     = make_uint4(u[0], u[1], u[2], u[3]);
    *(uint4*)(sA + am * PA + ah * 8 + 4) = make_uint4(u[4], u[5], u[6], u[7]);
}

__device__ __forceinline__ void stA_regs(unsigned* sA, int am, int ah, float4 av0, float4 av1) {
    *(uint4*)(sA + am * PA + ah * 8) =
        make_uint4(f2tf(av0.x), f2tf(av0.y), f2tf(av0.z), f2tf(av0.w));
    *(uint4*)(sA + am * PA + ah * 8 + 4) =
        make_uint4(f2tf(av1.x), f2tf(av1.y), f2tf(av1.z), f2tf(av1.w));
}

__device__ __forceinline__ void stB_regs(unsigned* sB, int bk, int bn, float4 bv0, float4 bv1) {
    *(uint4*)(sB + bk * PB + bn) =
        make_uint4(f2tf(bv0.x), f2tf(bv0.y), f2tf(bv0.z), f2tf(bv0.w));
    *(uint4*)(sB + bk * PB + bn + 4) =
        make_uint4(f2tf(bv1.x), f2tf(bv1.y), f2tf(bv1.z), f2tf(bv1.w));
}

__device__ __forceinline__ void ldB_regs(const float* __restrict__ W, int ldw, int krow,
                                         int ncol0, int bk, int bn, float4& bv0, float4& bv1) {
    const float* p = W + (size_t)(krow + bk) * ldw + ncol0 + bn;
    bv0 = *(const float4*)p; bv1 = *(const float4*)(p + 4);
}

// ---------------------------------------------------------------------------
__global__ void cvt_kernel(const void* __restrict__ ei_raw, int E) {
    const long long* p64 = (const long long*)ei_raw;
    const int*       p32 = (const int*)ei_raw;
    bool is64 = true;
#pragma unroll
    for (int j = 0; j < 4; j++) {
        long long v = p64[j];
        if (v < 0 || v >= NN) is64 = false;
    }
    int i = blockIdx.x * 256 + threadIdx.x;
    if (i < E) {
        int s, d;
        if (is64) { s = (int)p64[i]; d = (int)p64[(size_t)E + i]; }
        else      { s = p32[i];      d = p32[(size_t)E + i]; }
        g_src[i] = min(max(s, 0), NN - 1);
        g_dst[i] = min(max(d, 0), NN - 1);
    }
}

__global__ void zero_kernel(int Nn) {
    size_t i = (size_t)blockIdx.x * 256 + threadIdx.x;
    size_t nagg4 = (size_t)Nn * D / 4;
    size_t ncnt4 = (size_t)Nn / 4;
    if (i < nagg4) {
        ((float4*)g_agg)[i] = make_float4(0.f, 0.f, 0.f, 0.f);
    } else if (i - nagg4 < ncnt4) {
        ((float4*)g_cnt)[i - nagg4] = make_float4(0.f, 0.f, 0.f, 0.f);
    }
}

// ---------------------------------------------------------------------------
// Edge kernel: 128-edge tiles, tf32 tensor-core MLP, scatter-add.
// ---------------------------------------------------------------------------
__global__ __launch_bounds__(256)
void edge_kernel(const float* __restrict__ x, const float* __restrict__ ea,
                 const float* __restrict__ W1, const float* __restrict__ b1,
                 const float* __restrict__ W2, const float* __restrict__ b2,
                 const float* __restrict__ W3, const float* __restrict__ b3,
                 int E) {
    extern __shared__ float smf[];
    float*    sM  = smf;                              // 128 x PM fp32
    unsigned* sA  = (unsigned*)(smf + 128 * PM);      // 128 x PA tf32
    unsigned* sB  = sA + 128 * PA;                    // 16 x PB tf32
    int*      sSrc = (int*)(sB + 16 * PB);            // 128
    int*      sDst = sSrc + 128;                      // 128

    const int tid = threadIdx.x;
    const int e0  = blockIdx.x * 128;
    const int nE  = min(128, E - e0);

    if (tid < 128) {
        if (tid < nE) { sSrc[tid] = g_src[e0 + tid]; sDst[tid] = g_dst[e0 + tid]; }
        else          { sSrc[tid] = 0;               sDst[tid] = 0; }
    }
    __syncthreads();
    if (tid < nE) atomicAdd(&g_cnt[sDst[tid]], 1.0f);

    const int lane = tid & 31, wid = tid >> 5;
    const int warp_m = (wid & 3) * 32, warp_n = (wid >> 2) * 64;
    const int am = tid & 127, ah = tid >> 7;          // A staging role
    const int bk = tid >> 4,  bn = (tid & 15) * 8;    // B staging role

    float acc[2][8][4];
    acc_zero(acc);
    float4 av0, av1, bv0, bv1;

    // A-gather loader for GEMM1 (feats = [x[src] | x[dst] | ea])
    auto ldA1 = [&](int kc) {
        int kg = kc + ah * 8;
        if (am < nE) {
            const float* p;
            if (kg < 128)      p = x + (size_t)sSrc[am] * D + kg;
            else if (kg < 256) p = x + (size_t)sDst[am] * D + (kg - 128);
            else               p = ea + (size_t)(e0 + am) * DE + (kg - 256);
            av0 = *(const float4*)p; av1 = *(const float4*)(p + 4);
        } else {
            av0 = av1 = make_float4(0.f, 0.f, 0.f, 0.f);
        }
    };

    // ---------------- GEMM1: feats[128x288] @ W1 ----------------
    ldA1(0);
    ldB_regs(W1, D, 0, 0, bk, bn, bv0, bv1);
#pragma unroll 1
    for (int kc = 0; kc < KF; kc += 16) {
        __syncthreads();
        stA_regs(sA, am, ah, av0, av1);
        stB_regs(sB, bk, bn, bv0, bv1);
        if (kc + 16 < KF) { ldA1(kc + 16); ldB_regs(W1, D, kc + 16, 0, bk, bn, bv0, bv1); }
        __syncthreads();
        wmma_chunk(acc, sA, sB, warp_m, warp_n, lane);
    }
    ldB_regs(W2, D, 0, 0, bk, bn, bv0, bv1);   // prefetch W2 chunk 0
    __syncthreads();                            // all warps done with sA/sB
    epi_store(acc, sM, b1, 0, warp_m, warp_n, lane, false);
    acc_zero(acc);

    // ---------------- GEMM2: sigmoid(M1 @ W2 + b2) ----------------
#pragma unroll 1
    for (int kc = 0; kc < D; kc += 16) {
        __syncthreads();                        // sM visible / sA free
        stageA_sm(sM, sA, kc, am, ah);
        stB_regs(sB, bk, bn, bv0, bv1);
        if (kc + 16 < D) ldB_regs(W2, D, kc + 16, 0, bk, bn, bv0, bv1);
        __syncthreads();
        wmma_chunk(acc, sA, sB, warp_m, warp_n, lane);
    }
    ldB_regs(W3, D, 0, 0, bk, bn, bv0, bv1);
    __syncthreads();
    epi_store(acc, sM, b2, 0, warp_m, warp_n, lane, true);   // in-place sigmoid
    acc_zero(acc);

    // ---------------- GEMM3: M2 @ W3 + b3 ----------------
#pragma unroll 1
    for (int kc = 0; kc < D; kc += 16) {
        __syncthreads();
        stageA_sm(sM, sA, kc, am, ah);
        stB_regs(sB, bk, bn, bv0, bv1);
        if (kc + 16 < D) ldB_regs(W3, D, kc + 16, 0, bk, bn, bv0, bv1);
        __syncthreads();
        wmma_chunk(acc, sA, sB, warp_m, warp_n, lane);
    }
    __syncthreads();
    epi_store(acc, sM, b3, 0, warp_m, warp_n, lane, false);
    __syncthreads();

    // Scatter: row am, 64-col half ah -> g_agg[dst]
    if (am < nE) {
        float* base = g_agg + (size_t)sDst[am] * D + ah * 64;
        const float* row = sM + am * PM + ah * 64;
#pragma unroll
        for (int j = 0; j < 16; j++) {
            float4 v = make_float4(row[j * 4], row[j * 4 + 1], row[j * 4 + 2], row[j * 4 + 3]);
            atomicAdd((float4*)(base + j * 4), v);
        }
    }
}

// ---------------------------------------------------------------------------
// Node kernel: LN -> FF (tf32 tensor cores) -> LN
// ---------------------------------------------------------------------------
__global__ __launch_bounds__(256)
void node_kernel(const float* __restrict__ x,
                 const float* __restrict__ Wf1, const float* __restrict__ bf1,
                 const float* __restrict__ Wf2, const float* __restrict__ bf2,
                 const float* __restrict__ g0, const float* __restrict__ be0,
                 const float* __restrict__ g1, const float* __restrict__ be1,
                 float* __restrict__ out, int Nn) {
    extern __shared__ float smf[];
    float*    sH = smf;                           // 128 x PM
    float*    sT = sH + 128 * PM;                 // 128 x PM
    unsigned* sA = (unsigned*)(sT + 128 * PM);    // 128 x PA
    unsigned* sB = sA + 128 * PA;                 // 16 x PB

    const int tid = threadIdx.x;
    const int lane = tid & 31, wid = tid >> 5;
    const int r0 = blockIdx.x * 128;
    const int nR = min(128, Nn - r0);
    const int warp_m = (wid & 3) * 32, warp_n = (wid >> 2) * 64;
    const int am = tid & 127, ah = tid >> 7;
    const int bk = tid >> 4,  bn = (tid & 15) * 8;

    // Phase 1: LN(x + agg/cnt) -> sH  (scalar strided: col = lane + 32*j)
    for (int r = wid; r < 128; r += 8) {
        if (r < nR) {
            int g = r0 + r;
            float inv = 1.0f / fmaxf(g_cnt[g], 1.0f);
            float v[4], s = 0.f, q = 0.f;
#pragma unroll
            for (int j = 0; j < 4; j++) {
                int c = lane + 32 * j;
                v[j] = x[(size_t)g * D + c] + g_agg[(size_t)g * D + c] * inv;
                s += v[j]; q += v[j] * v[j];
            }
#pragma unroll
            for (int o = 16; o > 0; o >>= 1) {
                s += __shfl_xor_sync(0xffffffffu, s, o);
                q += __shfl_xor_sync(0xffffffffu, q, o);
            }
            float mu = s * (1.0f / 128.0f);
            float rs = rsqrtf(q * (1.0f / 128.0f) - mu * mu + 1e-5f);
#pragma unroll
            for (int j = 0; j < 4; j++) {
                int c = lane + 32 * j;
                sH[r * PM + c] = (v[j] - mu) * rs * g0[c] + be0[c];
            }
        } else {
#pragma unroll
            for (int j = 0; j < 4; j++) sH[r * PM + lane + 32 * j] = 0.f;
        }
    }

    // Phase 2: ff = sigmoid(h@Wf1+bf1)@Wf2, 4 chunks of 128 hidden cols
    float acc2[2][8][4];
    acc_zero(acc2);
    float4 bv0, bv1;

#pragma unroll 1
    for (int c = 0; c < 4; c++) {
        float acc[2][8][4];
        acc_zero(acc);
        ldB_regs(Wf1, HID, 0, c * 128, bk, bn, bv0, bv1);
#pragma unroll 1
        for (int kc = 0; kc < D; kc += 16) {          // T = H @ Wf1[:, c*128:+128]
            __syncthreads();
            stageA_sm(sH, sA, kc, am, ah);
            stB_regs(sB, bk, bn, bv0, bv1);
            if (kc + 16 < D) ldB_regs(Wf1, HID, kc + 16, c * 128, bk, bn, bv0, bv1);
            __syncthreads();
            wmma_chunk(acc, sA, sB, warp_m, warp_n, lane);
        }
        ldB_regs(Wf2, D, c * 128, 0, bk, bn, bv0, bv1);
        __syncthreads();
        epi_store(acc, sT, bf1, c * 128, warp_m, warp_n, lane, true);
#pragma unroll 1
        for (int kc = 0; kc < D; kc += 16) {          // acc2 += T @ Wf2[c*128:+128, :]
            __syncthreads();
            stageA_sm(sT, sA, kc, am, ah);
            stB_regs(sB, bk, bn, bv0, bv1);
            if (kc + 16 < D) ldB_regs(Wf2, D, c * 128 + kc + 16, 0, bk, bn, bv0, bv1);
            __syncthreads();
            wmma_chunk(acc2, sA, sB, warp_m, warp_n, lane);
        }
    }
    __syncthreads();
    epi_store(acc2, sT, bf2, 0, warp_m, warp_n, lane, false);
    __syncthreads();

    // Phase 3: out = LN(h + ff)
    for (int r = wid; r < nR; r += 8) {
        float v[4], s = 0.f, q = 0.f;
#pragma unroll
        for (int j = 0; j < 4; j++) {
            int c = lane + 32 * j;
            v[j] = sH[r * PM + c] + sT[r * PM + c];
            s += v[j]; q += v[j] * v[j];
        }
#pragma unroll
        for (int o = 16; o > 0; o >>= 1) {
            s += __shfl_xor_sync(0xffffffffu, s, o);
            q += __shfl_xor_sync(0xffffffffu, q, o);
        }
        float mu = s * (1.0f / 128.0f);
        float rs = rsqrtf(q * (1.0f / 128.0f) - mu * mu + 1e-5f);
        int g = r0 + r;
#pragma unroll
        for (int j = 0; j < 4; j++) {
            int c = lane + 32 * j;
            out[(size_t)g * D + c] = (v[j] - mu) * rs * g1[c] + be1[c];
        }
    }
}

// ---------------------------------------------------------------------------
extern "C" void kernel_launch(void* const* d_in, const int* in_sizes, int n_in,
                              void* d_out, int out_size) {
    // Identify big tensors by element count: edge_attr (E*32) > x (N*128) > edge_index (2E).
    int i_big[3] = {0, 1, 2};
    for (int a = 0; a < 2; a++)
        for (int b = a + 1; b < 3; b++)
            if (in_sizes[i_big[b]] > in_sizes[i_big[a]]) {
                int t = i_big[a]; i_big[a] = i_big[b]; i_big[b] = t;
            }
    const float* ea = (const float*)d_in[i_big[0]];
    const float* x  = (const float*)d_in[i_big[1]];
    const void*  ei = d_in[i_big[2]];

    const float* W1  = (const float*)d_in[3];
    const float* b1  = (const float*)d_in[4];
    const float* W2  = (const float*)d_in[5];
    const float* b2  = (const float*)d_in[6];
    const float* W3  = (const float*)d_in[7];
    const float* b3  = (const float*)d_in[8];
    const float* Wf1 = (const float*)d_in[9];
    const float* bf1 = (const float*)d_in[10];
    const float* Wf2 = (const float*)d_in[11];
    const float* bf2 = (const float*)d_in[12];
    const float* g0  = (const float*)d_in[13];
    const float* be0 = (const float*)d_in[14];
    const float* g1  = (const float*)d_in[15];
    const float* be1 = (const float*)d_in[16];
    float* out = (float*)d_out;

    int E  = in_sizes[i_big[0]] / DE;
    int Nn = in_sizes[i_big[1]] / D;
    if (E > EMAX) E = EMAX;

    int smemE = (128 * PM + 128 * PA + 16 * PB) * (int)sizeof(float) + 256 * (int)sizeof(int);
    int smemN = (128 * PM * 2 + 128 * PA + 16 * PB) * (int)sizeof(float);
    cudaFuncSetAttribute(edge_kernel, cudaFuncAttributeMaxDynamicSharedMemorySize, smemE);
    cudaFuncSetAttribute(node_kernel, cudaFuncAttributeMaxDynamicSharedMemorySize, smemN);

    cvt_kernel<<<(E + 255) / 256, 256>>>(ei, E);
    size_t tot4 = (size_t)Nn * D / 4 + (size_t)Nn / 4;
    zero_kernel<<<(unsigned)((tot4 + 255) / 256), 256>>>(Nn);
    edge_kernel<<<(E + 127) / 128, 256, smemE>>>(x, ea, W1, b1, W2, b2, W3, b3, E);
    node_kernel<<<(Nn + 127) / 128, 256, smemN>>>(x, Wf1, bf1, Wf2, bf2,
                                                  g0, be0, g1, be1, out, Nn);
}